// round 8
// baseline (speedup 1.0000x reference)
#include <cuda_runtime.h>

#define B_SZ 8192
#define K_SZ 25
#define L_SZ 25
#define NTHREADS 128
#define ROWS_PT 8                 // batch rows per thread (four f32x2 pairs)
#define NPAIR 4
#define LSPLIT 8                  // l-chunks: 4,3,3,3,3,3,3,3
#define LCHUNK 4
#define TILE_ROWS (NTHREADS * ROWS_PT)   // 1024 rows per block
#define BN_EPS 1e-5f

typedef unsigned long long u64;

__device__ float g_sum[L_SZ];
__device__ float g_sumsq[L_SZ];
__device__ float g_xT[L_SZ * B_SZ];   // raw x, transposed [L][B]

// ---------- packed f32x2 helpers ----------
__device__ __forceinline__ u64 pack2(float a, float b) {
    u64 r;
    asm("mov.b64 %0, {%1, %2};" : "=l"(r) : "r"(__float_as_uint(a)), "r"(__float_as_uint(b)));
    return r;
}
__device__ __forceinline__ u64 dup2(float a) { return pack2(a, a); }
__device__ __forceinline__ float2 unpack2(u64 v) {
    unsigned lo, hi;
    asm("mov.b64 {%0, %1}, %2;" : "=r"(lo), "=r"(hi) : "l"(v));
    return make_float2(__uint_as_float(lo), __uint_as_float(hi));
}
__device__ __forceinline__ u64 ffma2(u64 a, u64 b, u64 c) {
    u64 d;
    asm("fma.rn.f32x2 %0, %1, %2, %3;" : "=l"(d) : "l"(a), "l"(b), "l"(c));
    return d;
}
__device__ __forceinline__ u64 add2(u64 a, u64 b) {
    u64 d;
    asm("add.rn.f32x2 %0, %1, %2;" : "=l"(d) : "l"(a), "l"(b));
    return d;
}
__device__ __forceinline__ u64 relu2(u64 v) {
    float2 f = unpack2(v);
    return pack2(fmaxf(f.x, 0.f), fmaxf(f.y, 0.f));
}

// ---------- kernel 1: fused stats + transpose + out-init ----------
__global__ void __launch_bounds__(128) prologue_kernel(
    const float* __restrict__ x,
    const float* __restrict__ beta,
    float* __restrict__ out)
{
    __shared__ float t[64][27];
    __shared__ float ps[4][32], pq[4][32];
    __shared__ float sbeta[L_SZ];
    const int tid  = threadIdx.x;
    const int base = blockIdx.x * 64;

    if (tid < L_SZ) sbeta[tid] = beta[tid];
    __syncthreads();

    #pragma unroll
    for (int i = tid; i < 64 * L_SZ; i += 128) {
        int r = i / L_SZ, c = i - r * L_SZ;
        t[r][c] = x[base * L_SZ + i];
        out[base * L_SZ + i] = sbeta[c];
    }
    __syncthreads();

    {
        const int c = tid & 31, g = tid >> 5;
        float s = 0.f, q = 0.f;
        if (c < L_SZ) {
            #pragma unroll
            for (int r = g; r < 64; r += 4) {
                float v = t[r][c];
                s += v;
                q = fmaf(v, v, q);
            }
        }
        ps[g][c] = s;
        pq[g][c] = q;
    }
    __syncthreads();
    if (tid < L_SZ) {
        float S = ps[0][tid] + ps[1][tid] + ps[2][tid] + ps[3][tid];
        float Q = pq[0][tid] + pq[1][tid] + pq[2][tid] + pq[3][tid];
        atomicAdd(&g_sum[tid], S);
        atomicAdd(&g_sumsq[tid], Q);
    }

    #pragma unroll
    for (int i = tid; i < L_SZ * 64; i += 128) {
        int l = i >> 6, r = i & 63;
        g_xT[l * B_SZ + base + r] = t[r][l];
    }
}

// ---------- kernel 2: fused tiny-MLP ensemble, x staged in smem ----------
__global__ void __launch_bounds__(NTHREADS, 4) mlp_kernel(
    const float* __restrict__ gamma, const float* __restrict__ bn_bias,
    const float* __restrict__ W1, const float* __restrict__ b1,
    const float* __restrict__ W2, const float* __restrict__ b2,
    const float* __restrict__ W3, const float* __restrict__ b3,
    const float* __restrict__ W4, const float* __restrict__ b4,
    const float* __restrict__ alpha,
    float* __restrict__ out)
{
    __shared__ __align__(16) u64 sW1[LCHUNK][8];
    __shared__ __align__(16) u64 sB1[LCHUNK][8];
    __shared__ __align__(16) u64 sW2[LCHUNK][8][8];
    __shared__ __align__(16) u64 sB2[LCHUNK][8];
    __shared__ __align__(16) u64 sW3[LCHUNK][6][8];
    __shared__ u64 sB3[LCHUNK][6];
    __shared__ __align__(16) u64 sW4[LCHUNK][6];
    __shared__ u64 sB4[LCHUNK];
    // x tile: per l, interleaved halves: float4 slot t   = rows 8t..8t+3
    //                                    float4 slot 128+t = rows 8t+4..8t+7
    __shared__ __align__(16) float sx[LCHUNK][TILE_ROWS];

    const int k      = blockIdx.y;
    const int tid    = threadIdx.x;
    const int z      = blockIdx.z;
    const int lstart = (z == 0) ? 0 : 4 + (z - 1) * 3;
    const int nl     = (z == 0) ? 4 : 3;
    const int bx     = blockIdx.x;

    // ---- x tile fill (coalesced LDG.128, interleaved-halves STS) ----
    for (int li = 0; li < nl; ++li) {
        const float4* src4 = (const float4*)(g_xT + (lstart + li) * B_SZ + bx * TILE_ROWS);
        float4* d = (float4*)sx[li];
        float4 v0 = src4[tid];
        float4 v1 = src4[tid + 128];
        d[((tid & 1) << 7) + (tid >> 1)] = v0;
        int i2 = tid + 128;
        d[((i2 & 1) << 7) + (i2 >> 1)] = v1;
    }

    // ---- weight fill (BN folded into W1/b1, alpha into W4/b4) ----
    {
        const float* pw = W1 + (k * L_SZ + lstart) * 8;
        const float* pb = b1 + (k * L_SZ + lstart) * 8;
        for (int i = tid; i < nl * 8; i += NTHREADS) {
            int gl = lstart + (i >> 3);
            float mean = g_sum[gl] * (1.f / (float)B_SZ);
            float var  = g_sumsq[gl] * (1.f / (float)B_SZ) - mean * mean;
            float sc   = gamma[gl] * rsqrtf(var + BN_EPS);
            float sh   = bn_bias[gl] - mean * sc;
            float w    = pw[i];
            ((u64*)sW1)[i] = dup2(w * sc);
            ((u64*)sB1)[i] = dup2(fmaf(w, sh, pb[i]));
        }
        const float* p = W2 + (k * L_SZ + lstart) * 64;
        for (int i = tid; i < nl * 64; i += NTHREADS) ((u64*)sW2)[i] = dup2(p[i]);
        p = b2 + (k * L_SZ + lstart) * 8;
        for (int i = tid; i < nl * 8; i += NTHREADS) ((u64*)sB2)[i] = dup2(p[i]);
        p = W3 + (k * L_SZ + lstart) * 48;
        for (int i = tid; i < nl * 48; i += NTHREADS) ((u64*)sW3)[i] = dup2(p[i]);
        p = b3 + (k * L_SZ + lstart) * 6;
        for (int i = tid; i < nl * 6; i += NTHREADS) ((u64*)sB3)[i] = dup2(p[i]);
        p = W4 + (k * L_SZ + lstart) * 6;
        for (int i = tid; i < nl * 6; i += NTHREADS) {
            int gl = lstart + i / 6;
            ((u64*)sW4)[i] = dup2(p[i] * alpha[gl * K_SZ + k]);
        }
        for (int i = tid; i < nl; i += NTHREADS) {
            int gl = lstart + i;
            sB4[i] = dup2(b4[k * L_SZ + gl] * alpha[gl * K_SZ + k]);
        }
    }
    __syncthreads();

    const int b0 = (bx * NTHREADS + tid) * ROWS_PT;
    u64 acc[NPAIR] = {0ULL, 0ULL, 0ULL, 0ULL};

    // 1-deep software pipeline on the smem x reads
    ulonglong2 xva = ((const ulonglong2*)sx[0])[tid];
    ulonglong2 xvb = ((const ulonglong2*)sx[0])[tid + 128];

    #pragma unroll 1
    for (int li = 0; li < nl; ++li) {
        ulonglong2 nxa, nxb;
        if (li + 1 < nl) {
            nxa = ((const ulonglong2*)sx[li + 1])[tid];
            nxb = ((const ulonglong2*)sx[li + 1])[tid + 128];
        }
        u64 xn[NPAIR] = {xva.x, xva.y, xvb.x, xvb.y};

        // layer 1: 1 -> 8 (BN pre-folded into weights)
        u64 h1[NPAIR][8];
        {
            const ulonglong2* w  = (const ulonglong2*)sW1[li];
            const ulonglong2* bb = (const ulonglong2*)sB1[li];
            #pragma unroll
            for (int t = 0; t < 4; ++t) {
                ulonglong2 wv = w[t], bv = bb[t];
                #pragma unroll
                for (int p = 0; p < NPAIR; ++p) {
                    h1[p][2*t]   = relu2(ffma2(xn[p], wv.x, bv.x));
                    h1[p][2*t+1] = relu2(ffma2(xn[p], wv.y, bv.y));
                }
            }
        }

        // layer 2: 8 -> 8
        u64 h2[NPAIR][8];
        #pragma unroll
        for (int i = 0; i < 8; ++i) {
            const ulonglong2* w = (const ulonglong2*)sW2[li][i];
            ulonglong2 w0 = w[0], w1 = w[1], w2 = w[2], w3 = w[3];
            u64 wj[8] = {w0.x, w0.y, w1.x, w1.y, w2.x, w2.y, w3.x, w3.y};
            u64 bi = sB2[li][i];
            u64 a[NPAIR] = {bi, bi, bi, bi};
            #pragma unroll
            for (int j = 0; j < 8; ++j)
                #pragma unroll
                for (int p = 0; p < NPAIR; ++p)
                    a[p] = ffma2(h1[p][j], wj[j], a[p]);
            #pragma unroll
            for (int p = 0; p < NPAIR; ++p) h2[p][i] = relu2(a[p]);
        }

        // layer 3: 8 -> 6
        u64 h3[NPAIR][6];
        #pragma unroll
        for (int i = 0; i < 6; ++i) {
            const ulonglong2* w = (const ulonglong2*)sW3[li][i];
            ulonglong2 w0 = w[0], w1 = w[1], w2 = w[2], w3 = w[3];
            u64 wj[8] = {w0.x, w0.y, w1.x, w1.y, w2.x, w2.y, w3.x, w3.y};
            u64 bi = sB3[li][i];
            u64 a[NPAIR] = {bi, bi, bi, bi};
            #pragma unroll
            for (int j = 0; j < 8; ++j)
                #pragma unroll
                for (int p = 0; p < NPAIR; ++p)
                    a[p] = ffma2(h2[p][j], wj[j], a[p]);
            #pragma unroll
            for (int p = 0; p < NPAIR; ++p) h3[p][i] = relu2(a[p]);
        }

        // layer 4 (alpha pre-folded)
        {
            const ulonglong2* w = (const ulonglong2*)sW4[li];
            ulonglong2 w0 = w[0], w1 = w[1], w2 = w[2];
            u64 wj[6] = {w0.x, w0.y, w1.x, w1.y, w2.x, w2.y};
            u64 bi = sB4[li];
            u64 f[NPAIR] = {bi, bi, bi, bi};
            #pragma unroll
            for (int j = 0; j < 6; ++j)
                #pragma unroll
                for (int p = 0; p < NPAIR; ++p)
                    f[p] = ffma2(h3[p][j], wj[j], f[p]);
            #pragma unroll
            for (int p = 0; p < NPAIR; ++p) acc[p] = add2(acc[p], f[p]);
        }
        xva = nxa;
        xvb = nxb;
    }

    #pragma unroll
    for (int p = 0; p < NPAIR; ++p) {
        float2 r = unpack2(acc[p]);
        atomicAdd(out + (b0 + 2*p + 0) * K_SZ + k, r.x);
        atomicAdd(out + (b0 + 2*p + 1) * K_SZ + k, r.y);
    }
}

extern "C" void kernel_launch(void* const* d_in, const int* in_sizes, int n_in,
                              void* d_out, int out_size) {
    const float* x      = (const float*)d_in[0];
    const float* gamma  = (const float*)d_in[1];
    const float* bnb    = (const float*)d_in[2];
    const float* W1     = (const float*)d_in[3];
    const float* b1     = (const float*)d_in[4];
    const float* W2     = (const float*)d_in[5];
    const float* b2     = (const float*)d_in[6];
    const float* W3     = (const float*)d_in[7];
    const float* b3     = (const float*)d_in[8];
    const float* W4     = (const float*)d_in[9];
    const float* b4     = (const float*)d_in[10];
    const float* alpha  = (const float*)d_in[11];
    const float* beta   = (const float*)d_in[12];
    float* out = (float*)d_out;

    void* p_sum = nullptr;
    void* p_sq  = nullptr;
    cudaGetSymbolAddress(&p_sum, g_sum);
    cudaGetSymbolAddress(&p_sq,  g_sumsq);
    cudaMemsetAsync(p_sum, 0, L_SZ * sizeof(float));
    cudaMemsetAsync(p_sq,  0, L_SZ * sizeof(float));

    prologue_kernel<<<B_SZ / 64, 128>>>(x, beta, out);
    mlp_kernel<<<dim3(B_SZ / TILE_ROWS, K_SZ, LSPLIT), NTHREADS>>>(
        gamma, bnb, W1, b1, W2, b2, W3, b3, W4, b4, alpha, out);
}

// round 10
// speedup vs baseline: 1.1854x; 1.1854x over previous
#include <cuda_runtime.h>

#define B_SZ 8192
#define K_SZ 25
#define L_SZ 25
#define NCELL 1024
#define BN_EPS 1e-5f

typedef unsigned long long u64;

__device__ float g_sum[L_SZ];
__device__ float g_sumsq[L_SZ];
__device__ unsigned g_minu[L_SZ];
__device__ unsigned g_maxu[L_SZ];
__device__ float g_xT[L_SZ * B_SZ];            // raw x, transposed [L][B]
__device__ float g_lpA[L_SZ], g_lpC[L_SZ];     // u = fma(x, A, C)
__device__ float g_lpXmin[L_SZ], g_lpH[L_SZ];  // xn-grid origin/step
__device__ float2 g_table[K_SZ * L_SZ * NCELL];// {alpha*f0, alpha*df} per cell

// ---------- packed f32x2 helpers ----------
__device__ __forceinline__ u64 pack2(float a, float b) {
    u64 r;
    asm("mov.b64 %0, {%1, %2};" : "=l"(r) : "r"(__float_as_uint(a)), "r"(__float_as_uint(b)));
    return r;
}
__device__ __forceinline__ u64 dup2(float a) { return pack2(a, a); }
__device__ __forceinline__ float2 unpack2(u64 v) {
    unsigned lo, hi;
    asm("mov.b64 {%0, %1}, %2;" : "=r"(lo), "=r"(hi) : "l"(v));
    return make_float2(__uint_as_float(lo), __uint_as_float(hi));
}
__device__ __forceinline__ u64 ffma2(u64 a, u64 b, u64 c) {
    u64 d;
    asm("fma.rn.f32x2 %0, %1, %2, %3;" : "=l"(d) : "l"(a), "l"(b), "l"(c));
    return d;
}
__device__ __forceinline__ u64 relu2(u64 v) {
    float2 f = unpack2(v);
    return pack2(fmaxf(f.x, 0.f), fmaxf(f.y, 0.f));
}

// order-preserving float->uint map (for atomicMin/Max)
__device__ __forceinline__ unsigned fmap(float f) {
    int i = __float_as_int(f);
    return (i < 0) ? ~(unsigned)i : ((unsigned)i | 0x80000000u);
}
__device__ __forceinline__ float funmap(unsigned u) {
    int i = (u & 0x80000000u) ? (int)(u & 0x7FFFFFFFu) : ~(int)u;
    return __int_as_float(i);
}

// ---------- kernel 1: stats(sum,sq,min,max) + transpose + out=beta ----------
__global__ void __launch_bounds__(128) prologue_kernel(
    const float* __restrict__ x,
    const float* __restrict__ beta,
    float* __restrict__ out)
{
    __shared__ float t[64][27];
    __shared__ float ps[4][32], pq[4][32], pmn[4][32], pmx[4][32];
    __shared__ float sbeta[L_SZ];
    const int tid  = threadIdx.x;
    const int base = blockIdx.x * 64;

    if (tid < L_SZ) sbeta[tid] = beta[tid];
    __syncthreads();

    #pragma unroll
    for (int i = tid; i < 64 * L_SZ; i += 128) {
        int r = i / L_SZ, c = i - r * L_SZ;
        t[r][c] = x[base * L_SZ + i];
        out[base * L_SZ + i] = sbeta[c];
    }
    __syncthreads();

    {
        const int c = tid & 31, g = tid >> 5;
        float s = 0.f, q = 0.f, mn = 3.0e38f, mx = -3.0e38f;
        if (c < L_SZ) {
            #pragma unroll
            for (int r = g; r < 64; r += 4) {
                float v = t[r][c];
                s += v;
                q = fmaf(v, v, q);
                mn = fminf(mn, v);
                mx = fmaxf(mx, v);
            }
        }
        ps[g][c] = s; pq[g][c] = q; pmn[g][c] = mn; pmx[g][c] = mx;
    }
    __syncthreads();
    if (tid < L_SZ) {
        float S = ps[0][tid] + ps[1][tid] + ps[2][tid] + ps[3][tid];
        float Q = pq[0][tid] + pq[1][tid] + pq[2][tid] + pq[3][tid];
        float MN = fminf(fminf(pmn[0][tid], pmn[1][tid]), fminf(pmn[2][tid], pmn[3][tid]));
        float MX = fmaxf(fmaxf(pmx[0][tid], pmx[1][tid]), fmaxf(pmx[2][tid], pmx[3][tid]));
        atomicAdd(&g_sum[tid], S);
        atomicAdd(&g_sumsq[tid], Q);
        atomicMin(&g_minu[tid], fmap(MN));
        atomicMax(&g_maxu[tid], fmap(MX));
    }

    #pragma unroll
    for (int i = tid; i < L_SZ * 64; i += 128) {
        int l = i >> 6, r = i & 63;
        g_xT[l * B_SZ + base + r] = t[r][l];
    }
}

// ---------- kernel 2: per-l grid parameters ----------
__global__ void lparam_kernel(const float* __restrict__ gamma,
                              const float* __restrict__ bn_bias) {
    int l = threadIdx.x;
    if (l >= L_SZ) return;
    float mean = g_sum[l] * (1.f / (float)B_SZ);
    float var  = g_sumsq[l] * (1.f / (float)B_SZ) - mean * mean;
    float sc   = gamma[l] * rsqrtf(var + BN_EPS);
    float sh   = bn_bias[l] - mean * sc;
    float xmin = funmap(g_minu[l]);
    float xmax = funmap(g_maxu[l]);
    float a1 = fmaf(sc, xmin, sh), a2 = fmaf(sc, xmax, sh);
    float xnmin = fminf(a1, a2), xnmax = fmaxf(a1, a2);
    float range = xnmax - xnmin;
    float h     = range / (float)NCELL;
    float inv_h = (float)NCELL / range;
    g_lpXmin[l] = xnmin;
    g_lpH[l]    = h;
    g_lpA[l]    = sc * inv_h;
    g_lpC[l]    = (sh - xnmin) * inv_h;
}

// ---------- kernel 3: tabulate each net on its grid ----------
__global__ void __launch_bounds__(128) build_kernel(
    const float* __restrict__ W1, const float* __restrict__ b1,
    const float* __restrict__ W2, const float* __restrict__ b2,
    const float* __restrict__ W3, const float* __restrict__ b3,
    const float* __restrict__ W4, const float* __restrict__ b4,
    const float* __restrict__ alpha)
{
    __shared__ __align__(16) u64 sw1[8], sb1[8], sw2[64], sb2[8], sw3[48], sb3[6], sw4[6];
    __shared__ u64 sb4;
    __shared__ float nodes[NCELL + 2];

    const int l = blockIdx.x, k = blockIdx.y, tid = threadIdx.x;
    const int nb = k * L_SZ + l;

    if (tid < 8)  sw1[tid] = dup2(W1[nb * 8 + tid]);
    if (tid < 8)  sb1[tid] = dup2(b1[nb * 8 + tid]);
    if (tid < 64) sw2[tid] = dup2(W2[nb * 64 + tid]);
    if (tid < 8)  sb2[tid] = dup2(b2[nb * 8 + tid]);
    if (tid < 48) sw3[tid] = dup2(W3[nb * 48 + tid]);
    if (tid < 6)  sb3[tid] = dup2(b3[nb * 6 + tid]);
    if (tid < 6)  sw4[tid] = dup2(W4[nb * 6 + tid]);
    if (tid == 0) sb4 = dup2(b4[nb]);
    __syncthreads();

    const float xnmin = g_lpXmin[l];
    const float h     = g_lpH[l];

    // evaluate node pairs (2i, 2i+1), packed f32x2
    for (int i = tid; i < NCELL / 2 + 1; i += 128) {
        float x0 = fmaf((float)(2 * i), h, xnmin);
        u64 xn = pack2(x0, x0 + h);

        u64 h1[8];
        #pragma unroll
        for (int j = 0; j < 8; ++j) h1[j] = relu2(ffma2(xn, sw1[j], sb1[j]));
        u64 h2[8];
        #pragma unroll
        for (int j = 0; j < 8; ++j) {
            u64 a = sb2[j];
            #pragma unroll
            for (int q = 0; q < 8; ++q) a = ffma2(h1[q], sw2[j * 8 + q], a);
            h2[j] = relu2(a);
        }
        u64 h3[6];
        #pragma unroll
        for (int j = 0; j < 6; ++j) {
            u64 a = sb3[j];
            #pragma unroll
            for (int q = 0; q < 8; ++q) a = ffma2(h2[q], sw3[j * 8 + q], a);
            h3[j] = relu2(a);
        }
        u64 f = sb4;
        #pragma unroll
        for (int j = 0; j < 6; ++j) f = ffma2(h3[j], sw4[j], f);

        float2 fv = unpack2(f);
        int n0 = 2 * i;
        if (n0 <= NCELL)     nodes[n0] = fv.x;
        if (n0 + 1 <= NCELL) nodes[n0 + 1] = fv.y;
    }
    __syncthreads();

    const float al = alpha[l * K_SZ + k];
    float2* dst = g_table + nb * NCELL;
    for (int i = tid; i < NCELL; i += 128) {
        float f0 = nodes[i], f1 = nodes[i + 1];
        dst[i] = make_float2(al * f0, al * (f1 - f0));
    }
}

// ---------- kernel 4: table-based evaluation ----------
__global__ void __launch_bounds__(128) eval_kernel(float* __restrict__ out) {
    __shared__ __align__(16) float2 tb[2][NCELL];   // double-buffered 8KB tables
    __shared__ float sA[L_SZ], sC[L_SZ];

    const int tid = threadIdx.x;
    const int k   = blockIdx.y;
    const int z   = blockIdx.z;
    const int lstart = (z == 0) ? 0 : 7 + (z - 1) * 6;
    const int nl     = (z == 0) ? 7 : 6;
    const int b0  = blockIdx.x * 2048 + tid * 16;

    if (tid < L_SZ) { sA[tid] = g_lpA[tid]; sC[tid] = g_lpC[tid]; }

    // fill buffer 0
    {
        const float4* src = (const float4*)(g_table + (k * L_SZ + lstart) * NCELL);
        float4* d4 = (float4*)tb[0];
        #pragma unroll
        for (int j = 0; j < 4; ++j) d4[tid + j * 128] = src[tid + j * 128];
    }
    __syncthreads();

    float acc[16];
    #pragma unroll
    for (int i = 0; i < 16; ++i) acc[i] = 0.f;

    #pragma unroll 1
    for (int li = 0; li < nl; ++li) {
        if (li + 1 < nl) {   // prefetch next table into other buffer
            const float4* src = (const float4*)(g_table + (k * L_SZ + lstart + li + 1) * NCELL);
            float4* d4 = (float4*)tb[(li + 1) & 1];
            #pragma unroll
            for (int j = 0; j < 4; ++j) d4[tid + j * 128] = src[tid + j * 128];
        }
        const float2* T = tb[li & 1];
        const float A = sA[lstart + li], C = sC[lstart + li];
        const float4* xp = (const float4*)(g_xT + (lstart + li) * B_SZ + b0);
        #pragma unroll
        for (int q = 0; q < 4; ++q) {
            float4 xv = xp[q];
            float xs[4] = {xv.x, xv.y, xv.z, xv.w};
            #pragma unroll
            for (int c = 0; c < 4; ++c) {
                float u = fmaf(xs[c], A, C);
                int idx = __float2int_rd(u);
                idx = min(max(idx, 0), NCELL - 1);
                float frac = u - (float)idx;
                float2 td = T[idx];
                acc[q * 4 + c] += fmaf(frac, td.y, td.x);
            }
        }
        __syncthreads();
    }

    #pragma unroll
    for (int i = 0; i < 16; ++i)
        atomicAdd(out + (b0 + i) * K_SZ + k, acc[i]);
}

extern "C" void kernel_launch(void* const* d_in, const int* in_sizes, int n_in,
                              void* d_out, int out_size) {
    const float* x      = (const float*)d_in[0];
    const float* gamma  = (const float*)d_in[1];
    const float* bnb    = (const float*)d_in[2];
    const float* W1     = (const float*)d_in[3];
    const float* b1     = (const float*)d_in[4];
    const float* W2     = (const float*)d_in[5];
    const float* b2     = (const float*)d_in[6];
    const float* W3     = (const float*)d_in[7];
    const float* b3     = (const float*)d_in[8];
    const float* W4     = (const float*)d_in[9];
    const float* b4     = (const float*)d_in[10];
    const float* alpha  = (const float*)d_in[11];
    const float* beta   = (const float*)d_in[12];
    float* out = (float*)d_out;

    void *p_sum, *p_sq, *p_mn, *p_mx;
    cudaGetSymbolAddress(&p_sum, g_sum);
    cudaGetSymbolAddress(&p_sq,  g_sumsq);
    cudaGetSymbolAddress(&p_mn,  g_minu);
    cudaGetSymbolAddress(&p_mx,  g_maxu);
    cudaMemsetAsync(p_sum, 0,    L_SZ * sizeof(float));
    cudaMemsetAsync(p_sq,  0,    L_SZ * sizeof(float));
    cudaMemsetAsync(p_mn,  0xFF, L_SZ * sizeof(unsigned));
    cudaMemsetAsync(p_mx,  0x00, L_SZ * sizeof(unsigned));

    prologue_kernel<<<B_SZ / 64, 128>>>(x, beta, out);
    lparam_kernel<<<1, 32>>>(gamma, bnb);
    build_kernel<<<dim3(L_SZ, K_SZ), 128>>>(W1, b1, W2, b2, W3, b3, W4, b4, alpha);
    eval_kernel<<<dim3(B_SZ / 2048, K_SZ, 4), 128>>>(out);
}